// round 7
// baseline (speedup 1.0000x reference)
#include <cuda_runtime.h>
#include <stdint.h>
#include <math.h>

// ============================================================================
// ContrastiveAlignmentLoss — JAX-semantics replication on GB300 (sm_103a).
// jax_threefry_partitionable=True semantics:
//   random_bits(key,32): elem p -> TF(key,(0,p)), bits = o0^o1
//   split(key,2): key_i = TF(key,(0,i))
// R7 = R6 (346.8us) + ONE delta: permutation chain (9 launches) fused into a
// single one-block kernel k_perm (keys + 2 stable bucket sorts + anchor prep).
// k_main is byte-identical to R6's.
// ============================================================================

#define NPTS   20000
#define SANCH  5000
#define NNEG   256
#define TPRE   8126464u      // 2^23 - 2^18
#define TBITS  0xF8000000u   // TPRE << 9
#define CANDMAX 1024
#define NBIN   2048
#define INV_TEMP (1.0f/0.07f)

typedef unsigned long long u64;

static __device__ uint32_t g_keys[6];    // kneg, sub1, sub2
static __device__ u64      g_packed[NPTS];
static __device__ u64      g_tmp[NPTS];
static __device__ int      g_val1[NPTS];
static __device__ int      g_labS[SANCH];
static __device__ float    g_pos[SANCH];
static __device__ float    g_zvS[SANCH * 64];
static __device__ double   g_loss;

// ---------------- Threefry-2x32, 20 rounds (JAX/Random123) -----------------
__device__ __forceinline__ void tf2x32(uint32_t k0, uint32_t k1,
                                       uint32_t c0, uint32_t c1,
                                       uint32_t& o0, uint32_t& o1) {
    uint32_t ks2 = k0 ^ k1 ^ 0x1BD11BDAu;
    uint32_t x0 = c0 + k0;
    uint32_t x1 = c1 + k1;
#define TF_R(r) { x0 += x1; x1 = __funnelshift_l(x1, x1, (r)); x1 ^= x0; }
    TF_R(13) TF_R(15) TF_R(26) TF_R(6)
    x0 += k1;  x1 += ks2 + 1u;
    TF_R(17) TF_R(29) TF_R(16) TF_R(24)
    x0 += ks2; x1 += k0 + 2u;
    TF_R(13) TF_R(15) TF_R(26) TF_R(6)
    x0 += k0;  x1 += k1 + 3u;
    TF_R(17) TF_R(29) TF_R(16) TF_R(24)
    x0 += k1;  x1 += ks2 + 4u;
    TF_R(13) TF_R(15) TF_R(26) TF_R(6)
    x0 += ks2; x1 += k0 + 5u;
#undef TF_R
    o0 = x0; o1 = x1;
}

// ---------------- fused permutation: keys + 2 stable sorts + anchor prep ----
__global__ __launch_bounds__(1024, 1)
void k_perm(const float* __restrict__ zv, const float* __restrict__ zi,
            const long long* __restrict__ lab) {
    __shared__ int hist[NBIN];
    __shared__ int base[NBIN];
    __shared__ int cur[NBIN];
    __shared__ u64 wbuf[32][64];
    __shared__ int wtot[32];

    const int tid  = threadIdx.x;
    const int lane = tid & 31;
    const int wd   = tid >> 5;

    // key derivation (thread 0) + loss reset
    if (tid == 0) {
        uint32_t kp0, kp1, kn0, kn1, r1k0, r1k1, s10, s11, s20, s21;
        tf2x32(0u, 1u, 0u, 0u, kp0, kp1);      // kperm
        tf2x32(0u, 1u, 0u, 1u, kn0, kn1);      // kneg
        tf2x32(kp0, kp1, 0u, 0u, r1k0, r1k1);  // key after round-1 split
        tf2x32(kp0, kp1, 0u, 1u, s10, s11);    // sub1
        tf2x32(r1k0, r1k1, 0u, 1u, s20, s21);  // sub2
        g_keys[0] = kn0; g_keys[1] = kn1;
        g_keys[2] = s10; g_keys[3] = s11;
        g_keys[4] = s20; g_keys[5] = s21;
        g_loss = 0.0;
        __threadfence();                       // g_keys visible to k_main
    }
    __syncthreads();

    for (int round = 1; round <= 2; round++) {
        const int kb = (round == 1) ? 2 : 4;
        for (int i = tid; i < NBIN; i += 1024) hist[i] = 0;
        __syncthreads();

        const uint32_t kk0 = g_keys[kb], kk1 = g_keys[kb + 1];
        for (int p = tid; p < NPTS; p += 1024) {
            uint32_t o0, o1;
            tf2x32(kk0, kk1, 0u, (uint32_t)p, o0, o1);
            uint32_t key = o0 ^ o1;
            g_packed[p] = (((u64)key) << 32) | (unsigned)p;   // unique => stable
            atomicAdd(&hist[key >> 21], 1);
        }
        __syncthreads();

        // exclusive scan of 2048 bins: 2 bins/thread + warp scan + warp totals
        int h0 = hist[2 * tid], h1 = hist[2 * tid + 1];
        int tsum = h0 + h1;
        int v = tsum;
#pragma unroll
        for (int off = 1; off < 32; off <<= 1) {
            int n = __shfl_up_sync(0xffffffffu, v, off);
            if (lane >= off) v += n;
        }
        if (lane == 31) wtot[wd] = v;
        __syncthreads();
        int wpre = 0;
        for (int w = 0; w < wd; w++) wpre += wtot[w];
        int excl = wpre + v - tsum;
        base[2 * tid] = excl;          cur[2 * tid] = excl;
        base[2 * tid + 1] = excl + h0; cur[2 * tid + 1] = excl + h0;
        __syncthreads();

        // scatter into buckets
        for (int p = tid; p < NPTS; p += 1024) {
            u64 pk = g_packed[p];
            int bin = (int)(pk >> 53);
            int pos = atomicAdd(&cur[bin], 1);
            g_tmp[pos] = pk;
        }
        __syncthreads();

        // per-bucket exact rank (warp per bucket); round 2 fuses anchor prep
        for (int w = wd; w < NBIN; w += 32) {
            int start = base[w], m = hist[w];
            if (m == 0) continue;
            if (round == 2 && start >= SANCH) continue;
            if (m <= 64) {
                for (int e = lane; e < m; e += 32) wbuf[wd][e] = g_tmp[start + e];
                __syncwarp();
                for (int e = lane; e < m; e += 32) {
                    u64 me = wbuf[wd][e];
                    int r = 0;
                    for (int f = 0; f < m; f++) r += (wbuf[wd][f] < me) ? 1 : 0;
                    int idx0 = (int)(me & 0xffffffffu);
                    int slot = start + r;
                    if (round == 1) {
                        g_val1[slot] = idx0;
                    } else if (slot < SANCH) {
                        int idx = g_val1[idx0];
                        const float4* a4 = (const float4*)(zv + (size_t)idx * 64);
                        const float4* b4 = (const float4*)(zi + (size_t)idx * 64);
                        float4*       o4 = (float4*)(g_zvS + (size_t)slot * 64);
                        float acc = 0.f;
#pragma unroll
                        for (int q = 0; q < 16; q++) {
                            float4 a = a4[q]; float4 b = b4[q];
                            acc += a.x * b.x + a.y * b.y + a.z * b.z + a.w * b.w;
                            o4[q] = a;
                        }
                        g_pos[slot]  = acc * INV_TEMP;
                        g_labS[slot] = (int)lab[idx];
                    }
                }
                __syncwarp();
            } else {   // pathological bucket (prob ~0): direct global path
                for (int e = lane; e < m; e += 32) {
                    u64 me = g_tmp[start + e];
                    int r = 0;
                    for (int f = 0; f < m; f++) r += (g_tmp[start + f] < me) ? 1 : 0;
                    int idx0 = (int)(me & 0xffffffffu);
                    int slot = start + r;
                    if (round == 1) {
                        g_val1[slot] = idx0;
                    } else if (slot < SANCH) {
                        int idx = g_val1[idx0];
                        const float4* a4 = (const float4*)(zv + (size_t)idx * 64);
                        const float4* b4 = (const float4*)(zi + (size_t)idx * 64);
                        float4*       o4 = (float4*)(g_zvS + (size_t)slot * 64);
                        float acc = 0.f;
#pragma unroll
                        for (int q = 0; q < 16; q++) {
                            float4 a = a4[q]; float4 b = b4[q];
                            acc += a.x * b.x + a.y * b.y + a.z * b.z + a.w * b.w;
                            o4[q] = a;
                        }
                        g_pos[slot]  = acc * INV_TEMP;
                        g_labS[slot] = (int)lab[idx];
                    }
                }
            }
        }
        __syncthreads();
    }
}

// ---------------- main: lean sweep + post label filter + top-256 + InfoNCE --
// (byte-identical to R6's k_main)
__global__ __launch_bounds__(256, 6)
void k_main(const float* __restrict__ zimg, const long long* __restrict__ lab) {
    __shared__ u64 cands[CANDMAX];     // (v - TPRE)<<32 | j  (unfiltered)
    __shared__ u64 cands2[CANDMAX];    // label-filtered
    __shared__ int hist[256];
    __shared__ int sel[NNEG];
    __shared__ u64 eqb[64];
    __shared__ int s_cnt, s_cnt2, s_cgt, s_eq, s_b1, s_nd;
    __shared__ float zrow[64];
    __shared__ float red[8];
    __shared__ float s_m;

    const int s   = blockIdx.x;
    const int tid = threadIdx.x;
    const int lane = tid & 31;
    const int cls = g_labS[s];

    if (tid == 0) { s_cnt = 0; s_cnt2 = 0; s_cgt = 0; s_eq = 0; }
    sel[tid] = 0;
    hist[tid] = 0;
    if (tid < 64) zrow[tid] = g_zvS[s * 64 + tid];
    __syncthreads();

    // ---- sweep: 20000 threefry, prefilter bits >= TBITS (label-free) --------
    const uint32_t k0 = g_keys[0], k1 = g_keys[1];
    const uint32_t base = (uint32_t)s * 20000u;
    for (int j = tid; j < NPTS; j += 256) {
        uint32_t o0, o1;
        tf2x32(k0, k1, 0u, base + (uint32_t)j, o0, o1);
        uint32_t bits = o0 ^ o1;
        if (bits >= TBITS) {                 // == (bits>>9) >= TPRE
            uint32_t v = bits >> 9;
            int q = atomicAdd(&s_cnt, 1);
            if (q < CANDMAX)
                cands[q] = (((u64)(v - TPRE)) << 32) | (unsigned)j;
        }
    }
    __syncthreads();

    // ---- label filter: multiset identical to masked sweep -------------------
    int cnt = s_cnt; if (cnt > CANDMAX) cnt = CANDMAX;
    for (int t = tid; t < cnt; t += 256) {
        u64 cd = cands[t];
        int j = (int)(cd & 0xffffffffu);
        if ((int)lab[j] != cls) {
            int q = atomicAdd(&s_cnt2, 1);
            cands2[q] = cd;
        }
    }
    __syncthreads();
    int cnt2 = s_cnt2;

    // ---- level-1 histogram on top 8 of the 18 prefiltered bits --------------
    for (int t = tid; t < cnt2; t += 256) {
        uint32_t u = (uint32_t)(cands2[t] >> 32);
        atomicAdd(&hist[u >> 10], 1);
    }
    __syncthreads();
    if (tid == 0) {
        int need = NNEG, b;
        for (b = 255; b > 0; b--) { int h = hist[b]; if (h >= need) break; need -= h; }
        s_b1 = b; s_nd = need;
    }
    __syncthreads();
    const int b1 = s_b1;

    for (int t = tid; t < cnt2; t += 256) {
        u64 cd = cands2[t];
        int bin = (int)((uint32_t)(cd >> 32) >> 10);
        if (bin > b1) {
            int q = atomicAdd(&s_cgt, 1);
            if (q < NNEG) sel[q] = (int)(cd & 0xffffffffu);
        } else if (bin == b1) {
            int q = atomicAdd(&s_eq, 1);
            if (q < 64) eqb[q] = cd;
        }
    }
    __syncthreads();
    if (tid == 0) {
        // take nd best from boundary bin: max value first, ties -> lowest j
        int cg = s_cgt, nd = s_nd, ec = s_eq; if (ec > 64) ec = 64;
        for (int r = 0; r < nd && cg < NNEG; r++) {
            int bi = -1; uint32_t bu = 0; uint32_t bj = 0xffffffffu;
            for (int t = 0; t < ec; t++) {
                uint32_t u = (uint32_t)(eqb[t] >> 32);
                uint32_t j = (uint32_t)(eqb[t] & 0xffffffffu);
                if (j == 0x00ffffffu) continue;
                if (u > bu || (u == bu && j < bj)) { bu = u; bj = j; bi = t; }
            }
            if (bi < 0) break;
            sel[cg++] = (int)bj;
            eqb[bi] = 0x00ffffffull;
        }
    }
    __syncthreads();

    // ---- similarities for the 256 selected negatives -------------------------
    float x;
    {
        int j = sel[tid];
        const float4* zi4 = (const float4*)(zimg + (size_t)j * 64);
        const float4* zr4 = (const float4*)zrow;
        float acc = 0.f;
#pragma unroll
        for (int q = 0; q < 16; q++) {
            float4 a = zi4[q]; float4 b = zr4[q];
            acc += a.x * b.x + a.y * b.y + a.z * b.z + a.w * b.w;
        }
        x = acc * INV_TEMP;
    }
    const float pos = g_pos[s];

    float m = x;
#pragma unroll
    for (int off = 16; off; off >>= 1) m = fmaxf(m, __shfl_xor_sync(0xffffffffu, m, off));
    if (lane == 0) red[tid >> 5] = m;
    __syncthreads();
    if (tid == 0) {
        float mm = pos;
#pragma unroll
        for (int w = 0; w < 8; w++) mm = fmaxf(mm, red[w]);
        s_m = mm;
    }
    __syncthreads();
    m = s_m;

    float e = expf(x - m);
#pragma unroll
    for (int off = 16; off; off >>= 1) e += __shfl_xor_sync(0xffffffffu, e, off);
    if (lane == 0) red[tid >> 5] = e;
    __syncthreads();
    if (tid == 0) {
        float ssum = expf(pos - m);
#pragma unroll
        for (int w = 0; w < 8; w++) ssum += red[w];
        atomicAdd(&g_loss, (double)(logf(ssum) + m - pos));
    }
}

__global__ void k_final(float* out) {
    out[0] = (float)(0.1 * g_loss / 5000.0);
}

// ---------------- launch ----------------------------------------------------
extern "C" void kernel_launch(void* const* d_in, const int* in_sizes, int n_in,
                              void* d_out, int out_size) {
    const float*     zv  = (const float*)d_in[0];
    const float*     zi  = (const float*)d_in[1];
    const long long* lab = (const long long*)d_in[2];

    k_perm<<<1, 1024>>>(zv, zi, lab);
    k_main<<<SANCH, 256>>>(zi, lab);
    k_final<<<1, 1>>>((float*)d_out);
}